// round 3
// baseline (speedup 1.0000x reference)
#include <cuda_runtime.h>
#include <math.h>

// Problem shape (fixed by the dataset)
#define B_DIM 256
#define K_DIM 512
#define D_DIM 1024
#define KPB   64                      // k rows per block (8 warps x 8 rows)
#define NBLK  (B_DIM * (K_DIM / KPB)) // 2048 blocks
#define INV_T 14.2857142857142857f    // 1/0.07

// Scratch (no allocations allowed). Partials are fully overwritten every
// launch; ticket returns to 0 at the end of every launch (graph-replay safe).
__device__ double2      g_part[NBLK];
__device__ unsigned int g_ticket;      // zero-initialized at module load

__global__ __launch_bounds__(256, 5)
void fused_kernel(const float* __restrict__ bg_img,
                  const float* __restrict__ fg_pro,
                  const float* __restrict__ bg_pro,
                  float* __restrict__ out) {
    const int b    = blockIdx.x;
    const int ky   = blockIdx.y;
    const int tid  = threadIdx.x;
    const int warp = tid >> 5;
    const int lane = tid & 31;

    __shared__ float4 q_s[D_DIM / 4];        // normalized query row (4 KB)
    __shared__ float  w_red[16];             // 8 ss + 8 fd warp partials
    __shared__ double sacc[8];
    __shared__ double s_fg;
    __shared__ bool   s_is_last;

    // ---- cooperative normalize: thread t owns qrow[t] (float4) ----
    const float4* qrow = reinterpret_cast<const float4*>(bg_img + (size_t)b * D_DIM);
    float4 qv = qrow[tid];
    float ss = qv.x*qv.x + qv.y*qv.y + qv.z*qv.z + qv.w*qv.w;

    // fg dot folded in (only needed when ky==0): dot(q*inv,f) = inv*dot(q,f)
    float fd = 0.f;
    if (ky == 0) {
        const float4* frow = reinterpret_cast<const float4*>(fg_pro + (size_t)b * D_DIM);
        float4 f = frow[tid];
        fd = qv.x*f.x + qv.y*f.y + qv.z*f.z + qv.w*f.w;
    }

    #pragma unroll
    for (int o = 16; o; o >>= 1) {
        ss += __shfl_xor_sync(0xFFFFFFFFu, ss, o);
        fd += __shfl_xor_sync(0xFFFFFFFFu, fd, o);
    }
    if (lane == 0) { w_red[warp] = ss; w_red[8 + warp] = fd; }
    __syncthreads();

    float tss = 0.f, tfd = 0.f;
    #pragma unroll
    for (int i = 0; i < 8; i++) { tss += w_red[i]; tfd += w_red[8 + i]; }
    const float inv = 1.0f / sqrtf(tss);

    qv.x *= inv; qv.y *= inv; qv.z *= inv; qv.w *= inv;
    q_s[tid] = qv;
    if (tid == 0) s_fg = (ky == 0) ? (double)expf(tfd * inv * INV_T) : 0.0;
    __syncthreads();

    // ---- main streaming loop: warp owns 8 k rows, processed in pairs ----
    const int k0 = ky * KPB + warp * 8;
    const float* pbase = bg_pro + ((size_t)b * K_DIM + k0) * D_DIM;

    double acc = 0.0;
    #pragma unroll
    for (int kk = 0; kk < 8; kk += 2) {
        const float4* p0 = reinterpret_cast<const float4*>(pbase + (size_t)(kk    ) * D_DIM);
        const float4* p1 = reinterpret_cast<const float4*>(pbase + (size_t)(kk + 1) * D_DIM);
        float s0 = 0.f, s1 = 0.f;
        #pragma unroll
        for (int i = 0; i < 8; i++) {
            float4 qi = q_s[i * 32 + lane];     // one LDS feeds two k rows
            float4 a  = p0[i * 32 + lane];
            float4 c  = p1[i * 32 + lane];
            s0 = fmaf(qi.x, a.x, s0); s1 = fmaf(qi.x, c.x, s1);
            s0 = fmaf(qi.y, a.y, s0); s1 = fmaf(qi.y, c.y, s1);
            s0 = fmaf(qi.z, a.z, s0); s1 = fmaf(qi.z, c.z, s1);
            s0 = fmaf(qi.w, a.w, s0); s1 = fmaf(qi.w, c.w, s1);
        }
        #pragma unroll
        for (int o = 16; o; o >>= 1) {
            s0 += __shfl_xor_sync(0xFFFFFFFFu, s0, o);
            s1 += __shfl_xor_sync(0xFFFFFFFFu, s1, o);
        }
        if (lane == 0)
            acc += (double)expf(s0 * INV_T) + (double)expf(s1 * INV_T);
    }

    // ---- block reduce of pos partials, then ticketed last-block finish ----
    if (lane == 0) sacc[warp] = acc;
    __syncthreads();

    const int blk = blockIdx.y * gridDim.x + blockIdx.x;
    if (tid == 0) {
        double t = 0.0;
        #pragma unroll
        for (int i = 0; i < 8; i++) t += sacc[i];
        g_part[blk] = make_double2(t, s_fg);
        __threadfence();
        unsigned int done = atomicAdd(&g_ticket, 1u);
        s_is_last = (done == (unsigned int)(NBLK - 1));
    }
    __syncthreads();

    if (s_is_last) {
        const volatile double* vp = reinterpret_cast<const volatile double*>(g_part);
        double pos = 0.0, fg = 0.0;
        for (int i = tid; i < NBLK; i += 256) {
            pos += vp[2 * i + 0];
            fg  += vp[2 * i + 1];
        }
        #pragma unroll
        for (int o = 16; o; o >>= 1) {
            pos += __shfl_xor_sync(0xFFFFFFFFu, pos, o);
            fg  += __shfl_xor_sync(0xFFFFFFFFu, fg,  o);
        }
        __shared__ double w_pos[8], w_fg[8];
        if (lane == 0) { w_pos[warp] = pos; w_fg[warp] = fg; }
        __syncthreads();
        if (tid == 0) {
            double P = 0.0, F = 0.0;
            #pragma unroll
            for (int i = 0; i < 8; i++) { P += w_pos[i]; F += w_fg[i]; }
            // -log(pos/neg) = log1p(K * F / S)
            out[0] = (float)log1p(F * (double)K_DIM / P);
            g_ticket = 0;   // restore for next graph replay
        }
    }
}

extern "C" void kernel_launch(void* const* d_in, const int* in_sizes, int n_in,
                              void* d_out, int out_size) {
    const float* bg_img = (const float*)d_in[0];   // [B, D]
    const float* fg_pro = (const float*)d_in[1];   // [B, D]
    const float* bg_pro = (const float*)d_in[2];   // [B, K, D]
    float* out = (float*)d_out;

    dim3 grid(B_DIM, K_DIM / KPB);
    fused_kernel<<<grid, 256>>>(bg_img, fg_pro, bg_pro, out);
}

// round 4
// speedup vs baseline: 1.1290x; 1.1290x over previous
#include <cuda_runtime.h>
#include <math.h>

// Problem shape (fixed by the dataset)
#define B_DIM 256
#define K_DIM 512
#define D_DIM 1024
#define KPB   64                      // k rows per block (8 warps x 8 rows)
#define NBLK  (B_DIM * (K_DIM / KPB)) // 2048 blocks
#define INV_T 14.2857142857142857f    // 1/0.07

// Scratch (no allocations). Partials fully overwritten each launch; ticket
// returns to 0 at the end of every launch (graph-replay safe).
__device__ double2      g_part[NBLK];
__device__ unsigned int g_ticket;      // zero-initialized at module load

__global__ __launch_bounds__(256, 4)
void fused_kernel(const float* __restrict__ bg_img,
                  const float* __restrict__ fg_pro,
                  const float* __restrict__ bg_pro,
                  float* __restrict__ out) {
    const int b    = blockIdx.x;
    const int ky   = blockIdx.y;
    const int tid  = threadIdx.x;
    const int warp = tid >> 5;
    const int lane = tid & 31;

    __shared__ float4 q_s[D_DIM / 4];        // normalized query row (4 KB)
    __shared__ float  w_red[16];
    __shared__ double sacc[8];
    __shared__ double s_fg;
    __shared__ bool   s_is_last;

    // ---- cooperative normalize: thread t owns qrow[t] (float4) ----
    const float4* qrow = reinterpret_cast<const float4*>(bg_img + (size_t)b * D_DIM);
    float4 qv = qrow[tid];
    float ss = qv.x*qv.x + qv.y*qv.y + qv.z*qv.z + qv.w*qv.w;

    // fg dot folded in (only ky==0): dot(q*inv,f) = inv*dot(q,f)
    float fd = 0.f;
    if (ky == 0) {
        const float4* frow = reinterpret_cast<const float4*>(fg_pro + (size_t)b * D_DIM);
        float4 f = frow[tid];
        fd = qv.x*f.x + qv.y*f.y + qv.z*f.z + qv.w*f.w;
    }
    #pragma unroll
    for (int o = 16; o; o >>= 1) {
        ss += __shfl_xor_sync(0xFFFFFFFFu, ss, o);
        fd += __shfl_xor_sync(0xFFFFFFFFu, fd, o);
    }
    if (lane == 0) { w_red[warp] = ss; w_red[8 + warp] = fd; }
    __syncthreads();

    float tss = 0.f, tfd = 0.f;
    #pragma unroll
    for (int i = 0; i < 8; i++) { tss += w_red[i]; tfd += w_red[8 + i]; }
    const float inv = 1.0f / sqrtf(tss);

    qv.x *= inv; qv.y *= inv; qv.z *= inv; qv.w *= inv;
    q_s[tid] = qv;
    if (tid == 0) s_fg = (ky == 0) ? (double)expf(tfd * inv * INV_T) : 0.0;
    __syncthreads();

    // ---- hot loop: pure LDG/LDS/FFMA, no cross-lane ops ----
    // Warp owns 8 k rows; per-lane partials s[0..7]; two groups of 4 rows.
    const int k0 = ky * KPB + warp * 8;
    const float* pbase = bg_pro + ((size_t)b * K_DIM + k0) * D_DIM;

    float s[8];
    #pragma unroll
    for (int j = 0; j < 8; j++) s[j] = 0.f;

    #pragma unroll
    for (int g = 0; g < 2; g++) {
        const float4* p0 = reinterpret_cast<const float4*>(pbase + (size_t)(g*4 + 0) * D_DIM);
        const float4* p1 = reinterpret_cast<const float4*>(pbase + (size_t)(g*4 + 1) * D_DIM);
        const float4* p2 = reinterpret_cast<const float4*>(pbase + (size_t)(g*4 + 2) * D_DIM);
        const float4* p3 = reinterpret_cast<const float4*>(pbase + (size_t)(g*4 + 3) * D_DIM);
        #pragma unroll
        for (int i = 0; i < 8; i++) {
            const int idx = i * 32 + lane;
            float4 qi = q_s[idx];
            float4 a0 = __ldcs(&p0[idx]);
            float4 a1 = __ldcs(&p1[idx]);
            float4 a2 = __ldcs(&p2[idx]);
            float4 a3 = __ldcs(&p3[idx]);
            s[g*4+0] = fmaf(qi.x, a0.x, s[g*4+0]);
            s[g*4+0] = fmaf(qi.y, a0.y, s[g*4+0]);
            s[g*4+0] = fmaf(qi.z, a0.z, s[g*4+0]);
            s[g*4+0] = fmaf(qi.w, a0.w, s[g*4+0]);
            s[g*4+1] = fmaf(qi.x, a1.x, s[g*4+1]);
            s[g*4+1] = fmaf(qi.y, a1.y, s[g*4+1]);
            s[g*4+1] = fmaf(qi.z, a1.z, s[g*4+1]);
            s[g*4+1] = fmaf(qi.w, a1.w, s[g*4+1]);
            s[g*4+2] = fmaf(qi.x, a2.x, s[g*4+2]);
            s[g*4+2] = fmaf(qi.y, a2.y, s[g*4+2]);
            s[g*4+2] = fmaf(qi.z, a2.z, s[g*4+2]);
            s[g*4+2] = fmaf(qi.w, a2.w, s[g*4+2]);
            s[g*4+3] = fmaf(qi.x, a3.x, s[g*4+3]);
            s[g*4+3] = fmaf(qi.y, a3.y, s[g*4+3]);
            s[g*4+3] = fmaf(qi.z, a3.z, s[g*4+3]);
            s[g*4+3] = fmaf(qi.w, a3.w, s[g*4+3]);
        }
    }

    // ---- once-per-warp tail: 8 shfl-trees, exps spread across lanes ----
    double myexp = 0.0;
    #pragma unroll
    for (int j = 0; j < 8; j++) {
        float t = s[j];
        #pragma unroll
        for (int o = 16; o; o >>= 1) t += __shfl_xor_sync(0xFFFFFFFFu, t, o);
        if (lane == j) myexp = (double)expf(t * INV_T);   // lane j does row j's exp
    }
    #pragma unroll
    for (int o = 16; o; o >>= 1) myexp += __shfl_xor_sync(0xFFFFFFFFu, myexp, o);

    if (lane == 0) sacc[warp] = myexp;
    __syncthreads();

    // ---- block partial + ticketed last-block finish ----
    const int blk = blockIdx.y * gridDim.x + blockIdx.x;
    if (tid == 0) {
        double t = 0.0;
        #pragma unroll
        for (int i = 0; i < 8; i++) t += sacc[i];
        g_part[blk] = make_double2(t, s_fg);
        __threadfence();
        unsigned int done = atomicAdd(&g_ticket, 1u);
        s_is_last = (done == (unsigned int)(NBLK - 1));
    }
    __syncthreads();

    if (s_is_last) {
        const volatile double* vp = reinterpret_cast<const volatile double*>(g_part);
        double pos = 0.0, fg = 0.0;
        for (int i = tid; i < NBLK; i += 256) {
            pos += vp[2 * i + 0];
            fg  += vp[2 * i + 1];
        }
        #pragma unroll
        for (int o = 16; o; o >>= 1) {
            pos += __shfl_xor_sync(0xFFFFFFFFu, pos, o);
            fg  += __shfl_xor_sync(0xFFFFFFFFu, fg,  o);
        }
        __shared__ double w_pos[8], w_fg[8];
        if (lane == 0) { w_pos[warp] = pos; w_fg[warp] = fg; }
        __syncthreads();
        if (tid == 0) {
            double P = 0.0, F = 0.0;
            #pragma unroll
            for (int i = 0; i < 8; i++) { P += w_pos[i]; F += w_fg[i]; }
            // -log(pos/neg) = log1p(K * F / S)
            out[0] = (float)log1p(F * (double)K_DIM / P);
            g_ticket = 0;   // restore for next graph replay
        }
    }
}

extern "C" void kernel_launch(void* const* d_in, const int* in_sizes, int n_in,
                              void* d_out, int out_size) {
    const float* bg_img = (const float*)d_in[0];   // [B, D]
    const float* fg_pro = (const float*)d_in[1];   // [B, D]
    const float* bg_pro = (const float*)d_in[2];   // [B, K, D]
    float* out = (float*)d_out;

    dim3 grid(B_DIM, K_DIM / KPB);
    fused_kernel<<<grid, 256>>>(bg_img, fg_pro, bg_pro, out);
}

// round 5
// speedup vs baseline: 1.1725x; 1.0385x over previous
#include <cuda_runtime.h>
#include <math.h>

// Problem shape (fixed by the dataset)
#define B_DIM 256
#define K_DIM 512
#define D_DIM 1024
#define KPB   32                      // k rows per block (8 warps x 4 rows)
#define KYN   (K_DIM / KPB)           // 16
#define NBLK  (B_DIM * KYN)           // 4096 blocks
#define INV_T 14.2857142857142857f    // 1/0.07

// Scratch (no allocations). Partials fully overwritten each launch; ticket
// returns to 0 at the end of every launch (graph-replay safe).
__device__ double2      g_part[NBLK];
__device__ unsigned int g_ticket;      // zero-initialized at module load

// q_s is deliberately oversized (~45 KB used as smem ballast): it pins
// occupancy to exactly 4 blocks/SM (228KB carveout / ~46KB = 4), which makes
// the grid an integer number of waves (4096 / (148*4) = 6.92 ~ 7).
#define QS_PAD 2880                   // 2880 * 16B = 46080 B

__global__ __launch_bounds__(256, 4)
void fused_kernel(const float* __restrict__ bg_img,
                  const float* __restrict__ fg_pro,
                  const float* __restrict__ bg_pro,
                  float* __restrict__ out) {
    const int b    = blockIdx.x;
    const int ky   = blockIdx.y;
    const int tid  = threadIdx.x;
    const int warp = tid >> 5;
    const int lane = tid & 31;

    __shared__ float4 q_s[QS_PAD];           // first 256 entries = query row
    __shared__ float  w_red[16];
    __shared__ double sacc[8];
    __shared__ double s_fg;
    __shared__ bool   s_is_last;

    // ---- cooperative normalize: thread t owns qrow[t] (float4) ----
    const float4* qrow = reinterpret_cast<const float4*>(bg_img + (size_t)b * D_DIM);
    float4 qv = qrow[tid];
    float ss = qv.x*qv.x + qv.y*qv.y + qv.z*qv.z + qv.w*qv.w;

    // fg dot folded in (only ky==0): dot(q*inv,f) = inv*dot(q,f)
    float fd = 0.f;
    if (ky == 0) {
        const float4* frow = reinterpret_cast<const float4*>(fg_pro + (size_t)b * D_DIM);
        float4 f = frow[tid];
        fd = qv.x*f.x + qv.y*f.y + qv.z*f.z + qv.w*f.w;
    }
    #pragma unroll
    for (int o = 16; o; o >>= 1) {
        ss += __shfl_xor_sync(0xFFFFFFFFu, ss, o);
        fd += __shfl_xor_sync(0xFFFFFFFFu, fd, o);
    }
    if (lane == 0) { w_red[warp] = ss; w_red[8 + warp] = fd; }
    __syncthreads();

    float tss = 0.f, tfd = 0.f;
    #pragma unroll
    for (int i = 0; i < 8; i++) { tss += w_red[i]; tfd += w_red[8 + i]; }
    const float inv = 1.0f / sqrtf(tss);

    qv.x *= inv; qv.y *= inv; qv.z *= inv; qv.w *= inv;
    q_s[tid] = qv;
    if (tid == 0) s_fg = (ky == 0) ? (double)expf(tfd * inv * INV_T) : 0.0;
    __syncthreads();

    // ---- hot loop: warp owns 4 k rows; pure LDG/LDS/FFMA, no cross-lane ----
    const int k0 = ky * KPB + warp * 4;
    const float* pbase = bg_pro + ((size_t)b * K_DIM + k0) * D_DIM;
    const float4* p0 = reinterpret_cast<const float4*>(pbase + (size_t)0 * D_DIM);
    const float4* p1 = reinterpret_cast<const float4*>(pbase + (size_t)1 * D_DIM);
    const float4* p2 = reinterpret_cast<const float4*>(pbase + (size_t)2 * D_DIM);
    const float4* p3 = reinterpret_cast<const float4*>(pbase + (size_t)3 * D_DIM);

    float s0 = 0.f, s1 = 0.f, s2 = 0.f, s3 = 0.f;
    #pragma unroll
    for (int i = 0; i < 8; i++) {
        const int idx = i * 32 + lane;
        float4 qi = q_s[idx];
        float4 a0 = __ldcs(&p0[idx]);
        float4 a1 = __ldcs(&p1[idx]);
        float4 a2 = __ldcs(&p2[idx]);
        float4 a3 = __ldcs(&p3[idx]);
        s0 = fmaf(qi.x, a0.x, s0); s0 = fmaf(qi.y, a0.y, s0);
        s0 = fmaf(qi.z, a0.z, s0); s0 = fmaf(qi.w, a0.w, s0);
        s1 = fmaf(qi.x, a1.x, s1); s1 = fmaf(qi.y, a1.y, s1);
        s1 = fmaf(qi.z, a1.z, s1); s1 = fmaf(qi.w, a1.w, s1);
        s2 = fmaf(qi.x, a2.x, s2); s2 = fmaf(qi.y, a2.y, s2);
        s2 = fmaf(qi.z, a2.z, s2); s2 = fmaf(qi.w, a2.w, s2);
        s3 = fmaf(qi.x, a3.x, s3); s3 = fmaf(qi.y, a3.y, s3);
        s3 = fmaf(qi.z, a3.z, s3); s3 = fmaf(qi.w, a3.w, s3);
    }

    // ---- once-per-warp tail: 4 shfl-trees, exps spread across lanes ----
    double myexp = 0.0;
    {
        float t;
        t = s0;
        #pragma unroll
        for (int o = 16; o; o >>= 1) t += __shfl_xor_sync(0xFFFFFFFFu, t, o);
        if (lane == 0) myexp = (double)expf(t * INV_T);
        t = s1;
        #pragma unroll
        for (int o = 16; o; o >>= 1) t += __shfl_xor_sync(0xFFFFFFFFu, t, o);
        if (lane == 1) myexp = (double)expf(t * INV_T);
        t = s2;
        #pragma unroll
        for (int o = 16; o; o >>= 1) t += __shfl_xor_sync(0xFFFFFFFFu, t, o);
        if (lane == 2) myexp = (double)expf(t * INV_T);
        t = s3;
        #pragma unroll
        for (int o = 16; o; o >>= 1) t += __shfl_xor_sync(0xFFFFFFFFu, t, o);
        if (lane == 3) myexp = (double)expf(t * INV_T);
    }
    #pragma unroll
    for (int o = 16; o; o >>= 1) myexp += __shfl_xor_sync(0xFFFFFFFFu, myexp, o);

    if (lane == 0) sacc[warp] = myexp;
    __syncthreads();

    // ---- block partial + ticketed last-block finish ----
    const int blk = blockIdx.y * gridDim.x + blockIdx.x;
    if (tid == 0) {
        double t = 0.0;
        #pragma unroll
        for (int i = 0; i < 8; i++) t += sacc[i];
        g_part[blk] = make_double2(t, s_fg);
        __threadfence();
        unsigned int done = atomicAdd(&g_ticket, 1u);
        s_is_last = (done == (unsigned int)(NBLK - 1));
    }
    __syncthreads();

    if (s_is_last) {
        const volatile double* vp = reinterpret_cast<const volatile double*>(g_part);
        double pos = 0.0, fg = 0.0;
        for (int i = tid; i < NBLK; i += 256) {
            pos += vp[2 * i + 0];
            fg  += vp[2 * i + 1];
        }
        #pragma unroll
        for (int o = 16; o; o >>= 1) {
            pos += __shfl_xor_sync(0xFFFFFFFFu, pos, o);
            fg  += __shfl_xor_sync(0xFFFFFFFFu, fg,  o);
        }
        __shared__ double w_pos[8], w_fg[8];
        if (lane == 0) { w_pos[warp] = pos; w_fg[warp] = fg; }
        __syncthreads();
        if (tid == 0) {
            double P = 0.0, F = 0.0;
            #pragma unroll
            for (int i = 0; i < 8; i++) { P += w_pos[i]; F += w_fg[i]; }
            // -log(pos/neg) = log1p(K * F / S)
            out[0] = (float)log1p(F * (double)K_DIM / P);
            g_ticket = 0;   // restore for next graph replay
        }
    }
}

extern "C" void kernel_launch(void* const* d_in, const int* in_sizes, int n_in,
                              void* d_out, int out_size) {
    const float* bg_img = (const float*)d_in[0];   // [B, D]
    const float* fg_pro = (const float*)d_in[1];   // [B, D]
    const float* bg_pro = (const float*)d_in[2];   // [B, K, D]
    float* out = (float*)d_out;

    dim3 grid(B_DIM, KYN);
    fused_kernel<<<grid, 256>>>(bg_img, fg_pro, bg_pro, out);
}

// round 6
// speedup vs baseline: 1.2453x; 1.0621x over previous
#include <cuda_runtime.h>
#include <math.h>

// Problem shape (fixed by the dataset)
#define B_DIM 256
#define K_DIM 512
#define D_DIM 1024
#define KPB   32                      // k rows per tile (8 warps x 4 rows)
#define KYN   (K_DIM / KPB)           // 16 tiles per batch row
#define NTILE (B_DIM * KYN)           // 4096 tiles
#define GRID  592                     // 148 SMs x 4 resident blocks
#define INV_T 14.2857142857142857f    // 1/0.07

// Scratch (no allocations). Fully overwritten each launch; ticket returns
// to 0 at the end of every launch (graph-replay safe).
__device__ double2      g_part[GRID];
__device__ unsigned int g_ticket;      // zero-initialized at module load

// smem ballast: pins exactly 4 blocks/SM (228KB / ~46KB = 4) so all GRID
// blocks are co-resident and the persistent loop is perfectly balanced.
#define QS_PAD 2880                   // 2880 * 16B = 46080 B

__global__ __launch_bounds__(256, 4)
void fused_kernel(const float* __restrict__ bg_img,
                  const float* __restrict__ fg_pro,
                  const float* __restrict__ bg_pro,
                  float* __restrict__ out) {
    const int tid  = threadIdx.x;
    const int warp = tid >> 5;
    const int lane = tid & 31;

    __shared__ float4 q_s[QS_PAD];           // first 256 entries = query row
    __shared__ float  w_red[16];
    __shared__ double sacc[8];
    __shared__ bool   s_is_last;

    double acc_lane = 0.0;   // per-lane running sum of exp(bg_logit/T)
    double fg_acc   = 0.0;   // only meaningful on tid 0

    for (int t = blockIdx.x; t < NTILE; t += GRID) {
        const int b  = t >> 4;          // t / KYN
        const int ky = t & (KYN - 1);   // t % KYN

        // ---- cooperative normalize: thread tid owns qrow[tid] (float4) ----
        const float4* qrow = reinterpret_cast<const float4*>(bg_img + (size_t)b * D_DIM);
        float4 qv = qrow[tid];
        float ss = qv.x*qv.x + qv.y*qv.y + qv.z*qv.z + qv.w*qv.w;

        float fd = 0.f;
        if (ky == 0) {
            const float4* frow = reinterpret_cast<const float4*>(fg_pro + (size_t)b * D_DIM);
            float4 f = frow[tid];
            fd = qv.x*f.x + qv.y*f.y + qv.z*f.z + qv.w*f.w;
        }
        #pragma unroll
        for (int o = 16; o; o >>= 1) {
            ss += __shfl_xor_sync(0xFFFFFFFFu, ss, o);
            fd += __shfl_xor_sync(0xFFFFFFFFu, fd, o);
        }
        if (lane == 0) { w_red[warp] = ss; w_red[8 + warp] = fd; }
        __syncthreads();

        float tss = 0.f, tfd = 0.f;
        #pragma unroll
        for (int i = 0; i < 8; i++) { tss += w_red[i]; tfd += w_red[8 + i]; }
        const float inv = 1.0f / sqrtf(tss);

        qv.x *= inv; qv.y *= inv; qv.z *= inv; qv.w *= inv;
        q_s[tid] = qv;
        if (tid == 0 && ky == 0) fg_acc += (double)expf(tfd * inv * INV_T);
        __syncthreads();

        // ---- hot loop: warp owns 4 k rows; pure LDG/LDS/FFMA ----
        const int k0 = ky * KPB + warp * 4;
        const float* pbase = bg_pro + ((size_t)b * K_DIM + k0) * D_DIM;
        const float4* p0 = reinterpret_cast<const float4*>(pbase + (size_t)0 * D_DIM);
        const float4* p1 = reinterpret_cast<const float4*>(pbase + (size_t)1 * D_DIM);
        const float4* p2 = reinterpret_cast<const float4*>(pbase + (size_t)2 * D_DIM);
        const float4* p3 = reinterpret_cast<const float4*>(pbase + (size_t)3 * D_DIM);

        float s0 = 0.f, s1 = 0.f, s2 = 0.f, s3 = 0.f;
        #pragma unroll
        for (int i = 0; i < 8; i++) {
            const int idx = i * 32 + lane;
            float4 qi = q_s[idx];
            float4 a0 = __ldcs(&p0[idx]);
            float4 a1 = __ldcs(&p1[idx]);
            float4 a2 = __ldcs(&p2[idx]);
            float4 a3 = __ldcs(&p3[idx]);
            s0 = fmaf(qi.x, a0.x, s0); s0 = fmaf(qi.y, a0.y, s0);
            s0 = fmaf(qi.z, a0.z, s0); s0 = fmaf(qi.w, a0.w, s0);
            s1 = fmaf(qi.x, a1.x, s1); s1 = fmaf(qi.y, a1.y, s1);
            s1 = fmaf(qi.z, a1.z, s1); s1 = fmaf(qi.w, a1.w, s1);
            s2 = fmaf(qi.x, a2.x, s2); s2 = fmaf(qi.y, a2.y, s2);
            s2 = fmaf(qi.z, a2.z, s2); s2 = fmaf(qi.w, a2.w, s2);
            s3 = fmaf(qi.x, a3.x, s3); s3 = fmaf(qi.y, a3.y, s3);
            s3 = fmaf(qi.z, a3.z, s3); s3 = fmaf(qi.w, a3.w, s3);
        }

        // ---- per-tile tail: 4 shfl trees, exps land on lanes 0..3 ----
        float r;
        r = s0;
        #pragma unroll
        for (int o = 16; o; o >>= 1) r += __shfl_xor_sync(0xFFFFFFFFu, r, o);
        if (lane == 0) acc_lane += (double)expf(r * INV_T);
        r = s1;
        #pragma unroll
        for (int o = 16; o; o >>= 1) r += __shfl_xor_sync(0xFFFFFFFFu, r, o);
        if (lane == 1) acc_lane += (double)expf(r * INV_T);
        r = s2;
        #pragma unroll
        for (int o = 16; o; o >>= 1) r += __shfl_xor_sync(0xFFFFFFFFu, r, o);
        if (lane == 2) acc_lane += (double)expf(r * INV_T);
        r = s3;
        #pragma unroll
        for (int o = 16; o; o >>= 1) r += __shfl_xor_sync(0xFFFFFFFFu, r, o);
        if (lane == 3) acc_lane += (double)expf(r * INV_T);

        __syncthreads();   // protect q_s/w_red before next tile overwrites
    }

    // ---- once-per-block reduction + ticketed finish ----
    #pragma unroll
    for (int o = 16; o; o >>= 1)
        acc_lane += __shfl_xor_sync(0xFFFFFFFFu, acc_lane, o);
    if (lane == 0) sacc[warp] = acc_lane;
    __syncthreads();

    if (tid == 0) {
        double tsum = 0.0;
        #pragma unroll
        for (int i = 0; i < 8; i++) tsum += sacc[i];
        g_part[blockIdx.x] = make_double2(tsum, fg_acc);
        __threadfence();
        unsigned int done = atomicAdd(&g_ticket, 1u);
        s_is_last = (done == (unsigned int)(GRID - 1));
    }
    __syncthreads();

    if (s_is_last) {
        const volatile double* vp = reinterpret_cast<const volatile double*>(g_part);
        double pos = 0.0, fg = 0.0;
        for (int i = tid; i < GRID; i += 256) {
            pos += vp[2 * i + 0];
            fg  += vp[2 * i + 1];
        }
        #pragma unroll
        for (int o = 16; o; o >>= 1) {
            pos += __shfl_xor_sync(0xFFFFFFFFu, pos, o);
            fg  += __shfl_xor_sync(0xFFFFFFFFu, fg,  o);
        }
        __shared__ double w_pos[8], w_fg[8];
        if (lane == 0) { w_pos[warp] = pos; w_fg[warp] = fg; }
        __syncthreads();
        if (tid == 0) {
            double P = 0.0, F = 0.0;
            #pragma unroll
            for (int i = 0; i < 8; i++) { P += w_pos[i]; F += w_fg[i]; }
            // -log(pos/neg) = log1p(K * F / S)
            out[0] = (float)log1p(F * (double)K_DIM / P);
            g_ticket = 0;   // restore for next graph replay
        }
    }
}

extern "C" void kernel_launch(void* const* d_in, const int* in_sizes, int n_in,
                              void* d_out, int out_size) {
    const float* bg_img = (const float*)d_in[0];   // [B, D]
    const float* fg_pro = (const float*)d_in[1];   // [B, D]
    const float* bg_pro = (const float*)d_in[2];   // [B, K, D]
    float* out = (float*)d_out;

    fused_kernel<<<GRID, 256>>>(bg_img, fg_pro, bg_pro, out);
}